// round 6
// baseline (speedup 1.0000x reference)
#include <cuda_runtime.h>

// out[b,s,t] = sum_d input[b,t,s,d] * affine[d,t]
// B=8, T=128, S=256, D=1024, fp32.

#define B_ 8
#define T_ 128
#define S_ 256
#define D_ 1024
#define D4 (D_ / 4)   // 256 float4 per row

// Scratch: affine transposed to [T, D] for coalesced per-block row loads.
__device__ float d_affT[T_ * D_];

// 32x32 tiled transpose: d_affT[t*D + d] = affine[d*T + t]
__global__ __launch_bounds__(256)
void transpose_affine_kernel(const float* __restrict__ affine) {
    __shared__ float tile[32][33];
    const int d0 = blockIdx.x * 32;   // gridDim.x = D_/32 = 32
    const int t0 = blockIdx.y * 32;   // gridDim.y = T_/32 = 4
    const int x = threadIdx.x;        // 0..31
    const int y = threadIdx.y;        // 0..7

    #pragma unroll
    for (int i = 0; i < 32; i += 8)
        tile[y + i][x] = affine[(size_t)(d0 + y + i) * T_ + (t0 + x)];
    __syncthreads();
    #pragma unroll
    for (int i = 0; i < 32; i += 8)
        d_affT[(size_t)(t0 + y + i) * D_ + (d0 + x)] = tile[x][y + i];
}

__global__ __launch_bounds__(256)
void filtersum_kernel(const float* __restrict__ in,
                      float* __restrict__ out) {
    const int bt = blockIdx.x;          // 0..B_*T_-1
    const int b  = bt / T_;
    const int t  = bt % T_;
    const int tid  = threadIdx.x;
    const int lane = tid & 31;
    const int w    = tid >> 5;          // warp id, 0..7

    // Coalesced load of affine row t straight into registers (L2-hot, 4KB).
    float4 aff[8];
    const float4* at4 = reinterpret_cast<const float4*>(d_affT + (size_t)t * D_);
    #pragma unroll
    for (int c = 0; c < 8; c++)
        aff[c] = at4[lane + 32 * c];

    const float4* base = reinterpret_cast<const float4*>(in)
                       + (size_t)(b * T_ + t) * S_ * D4;

    // Lockstep mapping: at iteration j, the 8 warps cover rows [j*16, j*16+16).
    #pragma unroll 1
    for (int j = 0; j < 16; j++) {
        const int s = j * 16 + w * 2;
        const float4* r0 = base + (size_t)s * D4;
        const float4* r1 = r0 + D4;

        float acc0 = 0.0f, acc1 = 0.0f;
        #pragma unroll
        for (int c = 0; c < 8; c++) {
            float4 v0 = r0[lane + 32 * c];
            float4 v1 = r1[lane + 32 * c];
            acc0 = fmaf(v0.x, aff[c].x, acc0);
            acc0 = fmaf(v0.y, aff[c].y, acc0);
            acc0 = fmaf(v0.z, aff[c].z, acc0);
            acc0 = fmaf(v0.w, aff[c].w, acc0);
            acc1 = fmaf(v1.x, aff[c].x, acc1);
            acc1 = fmaf(v1.y, aff[c].y, acc1);
            acc1 = fmaf(v1.z, aff[c].z, acc1);
            acc1 = fmaf(v1.w, aff[c].w, acc1);
        }

        // warp reduction
        #pragma unroll
        for (int off = 16; off > 0; off >>= 1) {
            acc0 += __shfl_xor_sync(0xFFFFFFFFu, acc0, off);
            acc1 += __shfl_xor_sync(0xFFFFFFFFu, acc1, off);
        }

        if (lane == 0) {
            out[((size_t)b * S_ + s)     * T_ + t] = acc0;
            out[((size_t)b * S_ + s + 1) * T_ + t] = acc1;
        }
    }
}

extern "C" void kernel_launch(void* const* d_in, const int* in_sizes, int n_in,
                              void* d_out, int out_size) {
    const float* in     = (const float*)d_in[0];
    const float* affine = (const float*)d_in[1];
    float* out          = (float*)d_out;
    (void)in_sizes; (void)n_in; (void)out_size;

    dim3 tgrid(D_ / 32, T_ / 32);
    dim3 tblock(32, 8);
    transpose_affine_kernel<<<tgrid, tblock>>>(affine);

    dim3 grid(B_ * T_);
    dim3 block(256);
    filtersum_kernel<<<grid, block>>>(in, out);
}

// round 7
// speedup vs baseline: 1.0152x; 1.0152x over previous
#include <cuda_runtime.h>

// out[b,s,t] = sum_d input[b,t,s,d] * affine[d,t]
// B=8, T=128, S=256, D=1024, fp32.

#define B_ 8
#define T_ 128
#define S_ 256
#define D_ 1024
#define D4 (D_ / 4)   // 256 float4 per row

// Scratch: affine transposed to [T, D] for coalesced per-block row loads.
__device__ float d_affT[T_ * D_];

// 32x32 tiled transpose: d_affT[t*D + d] = affine[d*T + t]
__global__ __launch_bounds__(256)
void transpose_affine_kernel(const float* __restrict__ affine) {
    __shared__ float tile[32][33];
    const int d0 = blockIdx.x * 32;   // gridDim.x = D_/32 = 32
    const int t0 = blockIdx.y * 32;   // gridDim.y = T_/32 = 4
    const int x = threadIdx.x;        // 0..31
    const int y = threadIdx.y;        // 0..7

    #pragma unroll
    for (int i = 0; i < 32; i += 8)
        tile[y + i][x] = affine[(size_t)(d0 + y + i) * T_ + (t0 + x)];
    __syncthreads();
    #pragma unroll
    for (int i = 0; i < 32; i += 8)
        d_affT[(size_t)(t0 + y + i) * D_ + (d0 + x)] = tile[x][y + i];
}

__global__ __launch_bounds__(256)
void filtersum_kernel(const float* __restrict__ in,
                      float* __restrict__ out) {
    const int bt = blockIdx.x;          // 0..B_*T_-1
    const int b  = bt / T_;
    const int t  = bt % T_;
    const int tid  = threadIdx.x;
    const int lane = tid & 31;
    const int w    = tid >> 5;          // warp id, 0..7

    // All index math above is independent of the transpose; wait for the
    // predecessor (transpose) only now, so grid launch/scheduling overlaps it.
    cudaGridDependencySynchronize();

    // Coalesced load of affine row t straight into registers (L2-hot, 4KB).
    float4 aff[8];
    const float4* at4 = reinterpret_cast<const float4*>(d_affT + (size_t)t * D_);
    #pragma unroll
    for (int c = 0; c < 8; c++)
        aff[c] = at4[lane + 32 * c];

    const float4* base = reinterpret_cast<const float4*>(in)
                       + (size_t)(b * T_ + t) * S_ * D4;

    // Lockstep mapping: at iteration j, the 8 warps cover rows [j*16, j*16+16).
    #pragma unroll 1
    for (int j = 0; j < 16; j++) {
        const int s = j * 16 + w * 2;
        const float4* r0 = base + (size_t)s * D4;
        const float4* r1 = r0 + D4;

        float acc0 = 0.0f, acc1 = 0.0f;
        #pragma unroll
        for (int c = 0; c < 8; c++) {
            float4 v0 = r0[lane + 32 * c];
            float4 v1 = r1[lane + 32 * c];
            acc0 = fmaf(v0.x, aff[c].x, acc0);
            acc0 = fmaf(v0.y, aff[c].y, acc0);
            acc0 = fmaf(v0.z, aff[c].z, acc0);
            acc0 = fmaf(v0.w, aff[c].w, acc0);
            acc1 = fmaf(v1.x, aff[c].x, acc1);
            acc1 = fmaf(v1.y, aff[c].y, acc1);
            acc1 = fmaf(v1.z, aff[c].z, acc1);
            acc1 = fmaf(v1.w, aff[c].w, acc1);
        }

        // warp reduction
        #pragma unroll
        for (int off = 16; off > 0; off >>= 1) {
            acc0 += __shfl_xor_sync(0xFFFFFFFFu, acc0, off);
            acc1 += __shfl_xor_sync(0xFFFFFFFFu, acc1, off);
        }

        if (lane == 0) {
            out[((size_t)b * S_ + s)     * T_ + t] = acc0;
            out[((size_t)b * S_ + s + 1) * T_ + t] = acc1;
        }
    }
}

extern "C" void kernel_launch(void* const* d_in, const int* in_sizes, int n_in,
                              void* d_out, int out_size) {
    const float* in     = (const float*)d_in[0];
    const float* affine = (const float*)d_in[1];
    float* out          = (float*)d_out;
    (void)in_sizes; (void)n_in; (void)out_size;

    dim3 tgrid(D_ / 32, T_ / 32);
    dim3 tblock(32, 8);
    transpose_affine_kernel<<<tgrid, tblock>>>(affine);

    // Launch main kernel with programmatic dependent launch so its grid
    // launch + scheduling overlap the transpose instead of serializing.
    cudaLaunchAttribute attrs[1];
    attrs[0].id = cudaLaunchAttributeProgrammaticStreamSerialization;
    attrs[0].val.programmaticStreamSerializationAllowed = 1;

    cudaLaunchConfig_t cfg = {};
    cfg.gridDim  = dim3(B_ * T_);
    cfg.blockDim = dim3(256);
    cfg.dynamicSmemBytes = 0;
    cfg.stream = 0;
    cfg.attrs = attrs;
    cfg.numAttrs = 1;

    cudaLaunchKernelEx(&cfg, filtersum_kernel, in, out);
}